// round 15
// baseline (speedup 1.0000x reference)
#include <cuda_runtime.h>
#include <cuda_fp16.h>
#include <math.h>
#include <cstdint>

#define Bsz 32
#define Nn  100
#define Ee  9900
#define Hh  256
#define FIN 200
#define BE  (Bsz*Ee)    // 316800
#define BNr (Bsz*Nn)    // 3200
#define NCTA (BE/128)   // 2475

// ---------------- scratch (static device globals) ---------------------------
__device__ float g_h1[BNr*Hh];
__device__ float g_na[BNr*Hh];
__device__ float g_nb[BNr*Hh];
__device__ float g_as[BNr*Hh];
__device__ float g_ar[BNr*Hh];
__device__ __half g_xskipH[(size_t)BE*Hh];
__device__ __half g_y4H[(size_t)BE*Hh];
__device__ int   g_send[Ee];
__device__ int   g_recv[Ee];
__device__ float g_p3[(size_t)NCTA*256*2];
__device__ double g_chS[256], g_chQ[256];
__device__ float g_fcW[Hh*2];
__device__ float g_fcB[2];
// transposed fp16-split weight images [n][k], zero-padded beyond K:
// 0=m2W2(g1)  1=m4W1c(f23 s1)  2=m4W2(f23 s2)
// 3=m1W1(K200) 4=m1W2 5=m2W1a 6=m2W1b 7=m3W1 8=m3W2 9=m4W1a 10=m4W1b
#define NWIMG 11
__device__ __half g_WtHi[NWIMG][65536];
__device__ __half g_WtLo[NWIMG][65536];

__device__ __forceinline__ float elu_fast(float x) {
    float e = __expf(fminf(x, 0.f)) - 1.f;
    return x > 0.f ? x : e;
}
__device__ __forceinline__ uint32_t smem_u32(const void* p) {
    uint32_t a;
    asm("{ .reg .u64 t; cvta.to.shared.u64 t, %1; cvt.u32.u64 %0, t; }" : "=r"(a) : "l"(p));
    return a;
}
__device__ __forceinline__ uint32_t pack_h2(__half a, __half b) {
    __half2 h2 = __halves2half2(a, b);
    return *reinterpret_cast<uint32_t*>(&h2);
}

#define LDSM4(r, addr) \
    asm volatile("ldmatrix.sync.aligned.m8n8.x4.shared.b16 {%0,%1,%2,%3}, [%4];" \
        : "=r"((r)[0]), "=r"((r)[1]), "=r"((r)[2]), "=r"((r)[3]) : "r"(addr))

#define MMA16816(d, a, b0, b1) \
    asm volatile("mma.sync.aligned.m16n8k16.row.col.f32.f16.f16.f32 " \
        "{%0,%1,%2,%3},{%4,%5,%6,%7},{%8,%9},{%0,%1,%2,%3};" \
        : "+f"((d)[0]), "+f"((d)[1]), "+f"((d)[2]), "+f"((d)[3]) \
        : "r"((a)[0]), "r"((a)[1]), "r"((a)[2]), "r"((a)[3]), "r"(b0), "r"(b1))

#define CP16(dst, src) \
    asm volatile("cp.async.ca.shared.global [%0], [%1], 16;" :: "r"(dst), "l"(src))
#define CP_COMMIT() asm volatile("cp.async.commit_group;" ::: "memory")
#define CP_WAIT0()  asm volatile("cp.async.wait_group 0;" ::: "memory")

// ---------------- edge index extraction -------------------------------------
__global__ void build_idx_k(const float* __restrict__ rr, const float* __restrict__ rs) {
    int e = blockIdx.x * blockDim.x + threadIdx.x;
    if (e >= Ee) return;
    int r = 0, s = 0;
    for (int n = 0; n < Nn; n++) {
        if (rr[e*Nn + n] > 0.5f) r = n;
        if (rs[e*Nn + n] > 0.5f) s = n;
    }
    g_recv[e] = r;
    g_send[e] = s;
}

// ---------------- one-shot weight prep: all mats, transpose + split ---------
struct PrepArgs { const float* src[NWIMG]; int K[NWIMG]; };

__global__ void prep_all_k(PrepArgs pa) {
    int mi = blockIdx.z;
    const float* W = pa.src[mi];
    int K = pa.K[mi];
    __shared__ float t[32][33];
    int k0 = blockIdx.x * 32, n0 = blockIdx.y * 32;
    int tx = threadIdx.x, ty = threadIdx.y;
    int krow = k0 + ty;
    t[ty][tx] = (krow < K) ? W[krow * 256 + n0 + tx] : 0.f;
    __syncthreads();
    float v = t[tx][ty];            // element (k = k0+tx, n = n0+ty)
    __half h = __float2half_rn(v);
    __half l = __float2half_rn(v - __half2float(h));
    g_WtHi[mi][(n0 + ty) * 256 + k0 + tx] = h;
    g_WtLo[mi][(n0 + ty) * 256 + k0 + tx] = l;
}

// ---------------- node tensor GEMM: M=3200, 25 CTAs x 128 rows, 3-term ------
// A fp32 [M][K] (K=200 or 256, guarded), W from split images (zero-padded).
// Optional dual mode: gridDim.y=2 selects (widx,C) vs (widx2,C2).
#define ASTR  144
#define N_AHI 0
#define N_ALO 18432
#define N_BHI 36864
#define N_BLO 73728
#define NDS   110592

__global__ __launch_bounds__(512, 1)
void gemm_ntc(const float* __restrict__ A, int K,
              int widx, int widx2,
              const float* __restrict__ bias, int do_elu,
              float* __restrict__ C, float* __restrict__ C2)
{
    extern __shared__ char sm[];
    const int tid  = threadIdx.x;
    const int lane = tid & 31, w = tid >> 5;
    const int row0 = blockIdx.x * 128;
    int wi = widx;
    float* Cc = C;
    if (blockIdx.y == 1) { wi = widx2; Cc = C2; }
    const __half* WHi = g_WtHi[wi];
    const __half* WLo = g_WtLo[wi];
    const uint32_t sbase = smem_u32(sm);

    const int rowA = tid >> 2;
    const int q0   = (tid & 3) * 16;
    const float* arow = A + (size_t)(row0 + rowA) * K;

    const int m0w = (w & 3) * 32;
    const int n0w = (w >> 2) * 64;
    const int laneA_row = (lane & 7) + ((lane >> 3) & 1) * 8;
    const int laneA_k   = ((lane >> 4) & 1) * 8;
    const int laneB_row = (lane & 7) + ((lane >> 4) & 1) * 8;
    const int laneB_k   = ((lane >> 3) & 1) * 8;

    uint32_t aOff[2], bOff[4];
    #pragma unroll
    for (int i = 0; i < 2; i++)
        aOff[i] = (uint32_t)((m0w + i*16 + laneA_row) * ASTR + laneA_k * 2);
    #pragma unroll
    for (int jp = 0; jp < 4; jp++)
        bOff[jp] = (uint32_t)((n0w + jp*16 + laneB_row) * ASTR + laneB_k * 2);

    float acc[16][4];
    #pragma unroll
    for (int t = 0; t < 16; t++) { acc[t][0]=0.f; acc[t][1]=0.f; acc[t][2]=0.f; acc[t][3]=0.f; }

    #pragma unroll 1
    for (int c = 0; c < 4; ++c) {
        if (c) __syncthreads();     // previous chunk's MMAs done

        // ---- stage A (fp32, guarded) -> hi/lo fp16
        {
            char* dh = sm + N_AHI + rowA * ASTR + q0 * 2;
            char* dl = sm + N_ALO + rowA * ASTR + q0 * 2;
            #pragma unroll
            for (int it = 0; it < 2; ++it) {
                float v[8];
                #pragma unroll
                for (int e = 0; e < 8; ++e) {
                    int k = c * 64 + q0 + it * 8 + e;
                    v[e] = (k < K) ? arow[k] : 0.f;
                }
                uint4 oh, ol;
                __half h0, h1_;
                h0 = __float2half_rn(v[0]); h1_ = __float2half_rn(v[1]);
                oh.x = pack_h2(h0, h1_);
                ol.x = pack_h2(__float2half_rn(v[0]-__half2float(h0)), __float2half_rn(v[1]-__half2float(h1_)));
                h0 = __float2half_rn(v[2]); h1_ = __float2half_rn(v[3]);
                oh.y = pack_h2(h0, h1_);
                ol.y = pack_h2(__float2half_rn(v[2]-__half2float(h0)), __float2half_rn(v[3]-__half2float(h1_)));
                h0 = __float2half_rn(v[4]); h1_ = __float2half_rn(v[5]);
                oh.z = pack_h2(h0, h1_);
                ol.z = pack_h2(__float2half_rn(v[4]-__half2float(h0)), __float2half_rn(v[5]-__half2float(h1_)));
                h0 = __float2half_rn(v[6]); h1_ = __float2half_rn(v[7]);
                oh.w = pack_h2(h0, h1_);
                ol.w = pack_h2(__float2half_rn(v[6]-__half2float(h0)), __float2half_rn(v[7]-__half2float(h1_)));
                *(uint4*)(dh + it * 16) = oh;
                *(uint4*)(dl + it * 16) = ol;
            }
        }
        // ---- cp.async B hi+lo chunk
        #pragma unroll
        for (int i = 0; i < 8; ++i) {
            int seg = tid + i * 512;
            int isLo = seg >> 11;
            int rr = (seg >> 3) & 255, q = seg & 7;
            const __half* src = (isLo ? WLo : WHi) + (size_t)rr * 256 + c * 64 + q * 8;
            CP16(sbase + (isLo ? N_BLO : N_BHI) + rr * ASTR + q * 16, (const char*)src);
        }
        CP_COMMIT();
        CP_WAIT0();
        __syncthreads();

        // ---- MMA: 3-term (Ah*Bh + Ah*Bl + Al*Bh)
        #pragma unroll
        for (int ks = 0; ks < 4; ++ks) {
            uint32_t ah[2][4], al[2][4];
            #pragma unroll
            for (int i = 0; i < 2; i++) {
                LDSM4(ah[i], sbase + N_AHI + aOff[i] + ks * 32);
                LDSM4(al[i], sbase + N_ALO + aOff[i] + ks * 32);
            }
            #pragma unroll
            for (int jp = 0; jp < 4; jp++) {
                uint32_t bh4[4], bl4[4];
                LDSM4(bh4, sbase + N_BHI + bOff[jp] + ks * 32);
                LDSM4(bl4, sbase + N_BLO + bOff[jp] + ks * 32);
                MMA16816(acc[0*8+2*jp],   ah[0], bh4[0], bh4[1]);
                MMA16816(acc[0*8+2*jp+1], ah[0], bh4[2], bh4[3]);
                MMA16816(acc[1*8+2*jp],   ah[1], bh4[0], bh4[1]);
                MMA16816(acc[1*8+2*jp+1], ah[1], bh4[2], bh4[3]);
                MMA16816(acc[0*8+2*jp],   ah[0], bl4[0], bl4[1]);
                MMA16816(acc[0*8+2*jp+1], ah[0], bl4[2], bl4[3]);
                MMA16816(acc[1*8+2*jp],   ah[1], bl4[0], bl4[1]);
                MMA16816(acc[1*8+2*jp+1], ah[1], bl4[2], bl4[3]);
                MMA16816(acc[0*8+2*jp],   al[0], bh4[0], bh4[1]);
                MMA16816(acc[0*8+2*jp+1], al[0], bh4[2], bh4[3]);
                MMA16816(acc[1*8+2*jp],   al[1], bh4[0], bh4[1]);
                MMA16816(acc[1*8+2*jp+1], al[1], bh4[2], bh4[3]);
            }
        }
    }

    // ---- epilogue: fp32 + optional bias/ELU
    const int g  = lane >> 2;
    const int tg = lane & 3;
    #pragma unroll
    for (int i = 0; i < 2; i++) {
        #pragma unroll
        for (int j = 0; j < 8; j++) {
            int colg = n0w + j*8 + tg*2;
            float b0v = 0.f, b1v = 0.f;
            if (bias) { b0v = __ldg(bias + colg); b1v = __ldg(bias + colg + 1); }
            float* q = acc[i*8+j];
            int rlo = row0 + m0w + i*16 + g;
            int rhi = rlo + 8;
            float2 o0, o1;
            o0.x = q[0] + b0v; o0.y = q[1] + b1v;
            o1.x = q[2] + b0v; o1.y = q[3] + b1v;
            if (do_elu) {
                o0.x = elu_fast(o0.x); o0.y = elu_fast(o0.y);
                o1.x = elu_fast(o1.x); o1.y = elu_fast(o1.y);
            }
            *(float2*)(Cc + (size_t)rlo * 256 + colg) = o0;
            *(float2*)(Cc + (size_t)rhi * 256 + colg) = o1;
        }
    }
}

// ---------------- GEMM1: M128 x N256, 512 threads, 1-term W -----------------
#define BHIOF  18432
#define G1BUF  55296
#define G1DS   (2*G1BUF)   // 110592

__global__ __launch_bounds__(512, 1)
void gemm_g1(const __half* __restrict__ WtHi,
             const float* __restrict__ As_, const float* __restrict__ Ar_,
             const float* __restrict__ b1,
             const float* __restrict__ bias,
             __half* __restrict__ Cout)
{
    extern __shared__ char sm[];
    __shared__ int sidx[128], ridx[128];

    const int tid  = threadIdx.x;
    const int lane = tid & 31, w = tid >> 5;
    const int row0 = blockIdx.x * 128;
    const uint32_t sbase = smem_u32(sm);

    const int rowA = tid >> 2;
    const int q0   = (tid & 3) * 16;

    #define CPB1(cc, bf) do { \
        _Pragma("unroll") \
        for (int i = 0; i < 4; ++i) { \
            int seg = tid + i * 512; \
            int rr = (seg >> 3) & 255; \
            int q  = seg & 7; \
            const __half* src = WtHi + (size_t)rr * 256 + (cc) * 64 + q * 8; \
            CP16(sbase + (bf) * G1BUF + BHIOF + rr * ASTR + q * 16, (const char*)src); \
        } \
    } while (0)

    #define STSA1(cc, bf) do { \
        char* adst = sm + (bf) * G1BUF + rowA * ASTR + q0 * 2; \
        _Pragma("unroll") \
        for (int it = 0; it < 2; ++it) { \
            int k0 = (cc) * 64 + q0 + it * 8; \
            float4 s0 = *(const float4*)(As_ + si + k0); \
            float4 s1 = *(const float4*)(As_ + si + k0 + 4); \
            float4 r0 = *(const float4*)(Ar_ + ri + k0); \
            float4 r1 = *(const float4*)(Ar_ + ri + k0 + 4); \
            float4 c0 = *(const float4*)(b1 + k0); \
            float4 c1 = *(const float4*)(b1 + k0 + 4); \
            float v0=elu_fast(s0.x+r0.x+c0.x), v1=elu_fast(s0.y+r0.y+c0.y); \
            float v2=elu_fast(s0.z+r0.z+c0.z), v3=elu_fast(s0.w+r0.w+c0.w); \
            float v4=elu_fast(s1.x+r1.x+c1.x), v5=elu_fast(s1.y+r1.y+c1.y); \
            float v6=elu_fast(s1.z+r1.z+c1.z), v7=elu_fast(s1.w+r1.w+c1.w); \
            uint4 o; \
            o.x = pack_h2(__float2half_rn(v0), __float2half_rn(v1)); \
            o.y = pack_h2(__float2half_rn(v2), __float2half_rn(v3)); \
            o.z = pack_h2(__float2half_rn(v4), __float2half_rn(v5)); \
            o.w = pack_h2(__float2half_rn(v6), __float2half_rn(v7)); \
            *(uint4*)(adst + it * 16) = o; \
        } \
    } while (0)

    CPB1(0, 0);
    CP_COMMIT();
    if (tid < 128) {
        int row = row0 + tid;
        int b = row / Ee, e = row - b * Ee;
        sidx[tid] = (b * Nn + g_send[e]) * Hh;
        ridx[tid] = (b * Nn + g_recv[e]) * Hh;
    }
    __syncthreads();
    const int si = sidx[rowA], ri = ridx[rowA];
    STSA1(0, 0);

    const int m0w = (w & 3) * 32;
    const int n0w = (w >> 2) * 64;
    const int laneA_row = (lane & 7) + ((lane >> 3) & 1) * 8;
    const int laneA_k   = ((lane >> 4) & 1) * 8;
    const int laneB_row = (lane & 7) + ((lane >> 4) & 1) * 8;
    const int laneB_k   = ((lane >> 3) & 1) * 8;

    uint32_t aOff[2], bOff[4];
    #pragma unroll
    for (int i = 0; i < 2; i++)
        aOff[i] = (uint32_t)((m0w + i*16 + laneA_row) * ASTR + laneA_k * 2);
    #pragma unroll
    for (int jp = 0; jp < 4; jp++)
        bOff[jp] = (uint32_t)(BHIOF + (n0w + jp*16 + laneB_row) * ASTR + laneB_k * 2);

    float acc[16][4];
    #pragma unroll
    for (int t = 0; t < 16; t++) { acc[t][0]=0.f; acc[t][1]=0.f; acc[t][2]=0.f; acc[t][3]=0.f; }

    #pragma unroll 1
    for (int c = 0; c < 4; ++c) {
        const int cur = c & 1, nxt = cur ^ 1;
        CP_WAIT0();
        __syncthreads();
        if (c < 3) {
            CPB1(c + 1, nxt);
            CP_COMMIT();
            STSA1(c + 1, nxt);
        }
        const uint32_t base = sbase + cur * G1BUF;
        #pragma unroll
        for (int ks = 0; ks < 4; ++ks) {
            uint32_t ah[2][4];
            #pragma unroll
            for (int i = 0; i < 2; i++)
                LDSM4(ah[i], base + aOff[i] + ks * 32);
            #pragma unroll
            for (int jp = 0; jp < 4; jp++) {
                uint32_t bh4[4];
                LDSM4(bh4, base + bOff[jp] + ks * 32);
                MMA16816(acc[0*8+2*jp],   ah[0], bh4[0], bh4[1]);
                MMA16816(acc[0*8+2*jp+1], ah[0], bh4[2], bh4[3]);
                MMA16816(acc[1*8+2*jp],   ah[1], bh4[0], bh4[1]);
                MMA16816(acc[1*8+2*jp+1], ah[1], bh4[2], bh4[3]);
            }
        }
    }

    const int g  = lane >> 2;
    const int tg = lane & 3;
    #pragma unroll
    for (int i = 0; i < 2; i++) {
        #pragma unroll
        for (int j = 0; j < 8; j++) {
            int colg = n0w + j*8 + tg*2;
            float b0v = __ldg(bias + colg), b1v = __ldg(bias + colg + 1);
            float* q = acc[i*8+j];
            int rlo = row0 + m0w + i*16 + g;
            int rhi = rlo + 8;
            float o0 = elu_fast(q[0] + b0v), o1 = elu_fast(q[1] + b1v);
            float o2 = elu_fast(q[2] + b0v), o3 = elu_fast(q[3] + b1v);
            *(uint32_t*)(Cout + (size_t)rlo * 256 + colg) = pack_h2(__float2half_rn(o0), __float2half_rn(o1));
            *(uint32_t*)(Cout + (size_t)rhi * 256 + colg) = pack_h2(__float2half_rn(o2), __float2half_rn(o3));
        }
    }
    #undef CPB1
    #undef STSA1
}

// ---------------- fused GEMM2+GEMM3 (both stages 1-term W) ------------------
#define F_STG   67584
#define F_S1BUF 55296
#define F_S2BUF 36864
#define F_DS    (F_STG + 2*F_S1BUF)   // 178176

__global__ __launch_bounds__(512, 1)
void gemm_f23(const __half* __restrict__ AmatH,
              const __half* __restrict__ W1Hi,
              const __half* __restrict__ W2Hi,
              const float* __restrict__ As_, const float* __restrict__ Ar_,
              const float* __restrict__ b1, const float* __restrict__ bias,
              __half* __restrict__ Cout)
{
    extern __shared__ char sm[];
    __shared__ int sidx[128], ridx[128];

    const int tid  = threadIdx.x;
    const int lane = tid & 31, w = tid >> 5;
    const int row0 = blockIdx.x * 128;
    const uint32_t sbase = smem_u32(sm);

    #define CPA1(cc, bf) do { \
        _Pragma("unroll") \
        for (int i = 0; i < 2; ++i) { \
            int seg = tid + i * 512; \
            int rr = seg >> 3, q = seg & 7; \
            const __half* src = AmatH + (size_t)(row0 + rr) * 256 + (cc) * 64 + q * 8; \
            CP16(sbase + F_STG + (bf) * F_S1BUF + rr * ASTR + q * 16, (const char*)src); \
        } \
    } while (0)
    #define CPB1f(cc, bf) do { \
        _Pragma("unroll") \
        for (int i = 0; i < 4; ++i) { \
            int seg = tid + i * 512; \
            int rr = (seg >> 3) & 255, q = seg & 7; \
            const __half* src = W1Hi + (size_t)rr * 256 + (cc) * 64 + q * 8; \
            CP16(sbase + F_STG + (bf) * F_S1BUF + 18432 + rr * ASTR + q * 16, (const char*)src); \
        } \
    } while (0)
    #define CPB2(cc, bf) do { \
        _Pragma("unroll") \
        for (int i = 0; i < 4; ++i) { \
            int seg = tid + i * 512; \
            int rr = (seg >> 3) & 255, q = seg & 7; \
            const __half* src = W2Hi + (size_t)rr * 256 + (cc) * 64 + q * 8; \
            CP16(sbase + F_STG + (bf) * F_S2BUF + rr * ASTR + q * 16, (const char*)src); \
        } \
    } while (0)

    CPA1(0, 0);
    CPB1f(0, 0);
    CP_COMMIT();
    if (tid < 128) {
        int row = row0 + tid;
        int b = row / Ee, e = row - b * Ee;
        sidx[tid] = (b * Nn + g_send[e]) * Hh;
        ridx[tid] = (b * Nn + g_recv[e]) * Hh;
    }

    const int m0w = (w & 3) * 32;
    const int n0w = (w >> 2) * 64;
    const int laneA_row = (lane & 7) + ((lane >> 3) & 1) * 8;
    const int laneA_k   = ((lane >> 4) & 1) * 8;
    const int laneB_row = (lane & 7) + ((lane >> 4) & 1) * 8;
    const int laneB_k   = ((lane >> 3) & 1) * 8;

    uint32_t aOff1[2], bOff1[4];
    #pragma unroll
    for (int i = 0; i < 2; i++)
        aOff1[i] = (uint32_t)((m0w + i*16 + laneA_row) * ASTR + laneA_k * 2);
    #pragma unroll
    for (int jp = 0; jp < 4; jp++)
        bOff1[jp] = (uint32_t)(18432 + (n0w + jp*16 + laneB_row) * ASTR + laneB_k * 2);

    float acc[16][4];
    #pragma unroll
    for (int t = 0; t < 16; t++) { acc[t][0]=0.f; acc[t][1]=0.f; acc[t][2]=0.f; acc[t][3]=0.f; }

    // ---- stage-1 mainloop (1-term)
    #pragma unroll 1
    for (int c = 0; c < 4; ++c) {
        const int cur = c & 1, nxt = cur ^ 1;
        CP_WAIT0();
        __syncthreads();
        if (c < 3) {
            CPA1(c + 1, nxt);
            CPB1f(c + 1, nxt);
            CP_COMMIT();
        }
        const uint32_t base = sbase + F_STG + cur * F_S1BUF;
        #pragma unroll
        for (int ks = 0; ks < 4; ++ks) {
            uint32_t ah[2][4];
            #pragma unroll
            for (int i = 0; i < 2; i++)
                LDSM4(ah[i], base + aOff1[i] + ks * 32);
            #pragma unroll
            for (int jp = 0; jp < 4; jp++) {
                uint32_t bh4[4];
                LDSM4(bh4, base + bOff1[jp] + ks * 32);
                MMA16816(acc[0*8+2*jp],   ah[0], bh4[0], bh4[1]);
                MMA16816(acc[0*8+2*jp+1], ah[0], bh4[2], bh4[3]);
                MMA16816(acc[1*8+2*jp],   ah[1], bh4[0], bh4[1]);
                MMA16816(acc[1*8+2*jp+1], ah[1], bh4[2], bh4[3]);
            }
        }
    }
    __syncthreads();

    CPB2(0, 0);
    CP_COMMIT();

    // ---- build A2 = fp16(ELU(pre + As[s]+Ar[r]+b1)) into [0, 67584)
    const int g  = lane >> 2;
    const int tg = lane & 3;
    #pragma unroll
    for (int i = 0; i < 2; ++i) {
        int lr0 = m0w + i*16 + g;
        int lr1 = lr0 + 8;
        int s0i = sidx[lr0], r0i = ridx[lr0];
        int s1i = sidx[lr1], r1i = ridx[lr1];
        #pragma unroll
        for (int j = 0; j < 8; ++j) {
            int colg = n0w + j*8 + tg*2;
            float2 sa0 = *(const float2*)(As_ + s0i + colg);
            float2 ra0 = *(const float2*)(Ar_ + r0i + colg);
            float2 sa1 = *(const float2*)(As_ + s1i + colg);
            float2 ra1 = *(const float2*)(Ar_ + r1i + colg);
            float2 bb  = *(const float2*)(b1 + colg);
            float* q4 = acc[i*8+j];
            float v0 = elu_fast(q4[0] + sa0.x + ra0.x + bb.x);
            float v1 = elu_fast(q4[1] + sa0.y + ra0.y + bb.y);
            float v2 = elu_fast(q4[2] + sa1.x + ra1.x + bb.x);
            float v3 = elu_fast(q4[3] + sa1.y + ra1.y + bb.y);
            *(uint32_t*)(sm + lr0 * 528 + colg * 2) = pack_h2(__float2half_rn(v0), __float2half_rn(v1));
            *(uint32_t*)(sm + lr1 * 528 + colg * 2) = pack_h2(__float2half_rn(v2), __float2half_rn(v3));
        }
    }
    #pragma unroll
    for (int t = 0; t < 16; t++) { acc[t][0]=0.f; acc[t][1]=0.f; acc[t][2]=0.f; acc[t][3]=0.f; }

    uint32_t aOff2[2], bOff2[4];
    #pragma unroll
    for (int i = 0; i < 2; i++)
        aOff2[i] = (uint32_t)((m0w + i*16 + laneA_row) * 528 + laneA_k * 2);
    #pragma unroll
    for (int jp = 0; jp < 4; jp++)
        bOff2[jp] = (uint32_t)(F_STG + (n0w + jp*16 + laneB_row) * ASTR + laneB_k * 2);

    // ---- stage-2 mainloop (1-term, A2 resident)
    #pragma unroll 1
    for (int c = 0; c < 4; ++c) {
        const int cur = c & 1, nxt = cur ^ 1;
        CP_WAIT0();
        __syncthreads();
        if (c < 3) {
            CPB2(c + 1, nxt);
            CP_COMMIT();
        }
        const uint32_t koA = (uint32_t)(c * 128);
        const uint32_t bbase = sbase + cur * F_S2BUF;
        #pragma unroll
        for (int ks = 0; ks < 4; ++ks) {
            uint32_t ah[2][4];
            #pragma unroll
            for (int i = 0; i < 2; i++)
                LDSM4(ah[i], sbase + aOff2[i] + koA + ks * 32);
            #pragma unroll
            for (int jp = 0; jp < 4; jp++) {
                uint32_t bh4[4];
                LDSM4(bh4, bbase + bOff2[jp] + ks * 32);
                MMA16816(acc[0*8+2*jp],   ah[0], bh4[0], bh4[1]);
                MMA16816(acc[0*8+2*jp+1], ah[0], bh4[2], bh4[3]);
                MMA16816(acc[1*8+2*jp],   ah[1], bh4[0], bh4[1]);
                MMA16816(acc[1*8+2*jp+1], ah[1], bh4[2], bh4[3]);
            }
        }
    }

    // ---- epilogue: bias + ELU + fp16 stores + BN partials
    float cs[16], cq[16];
    #pragma unroll
    for (int t = 0; t < 16; ++t) { cs[t] = 0.f; cq[t] = 0.f; }
    #pragma unroll
    for (int i = 0; i < 2; i++) {
        #pragma unroll
        for (int j = 0; j < 8; j++) {
            int colg = n0w + j*8 + tg*2;
            float b0v = __ldg(bias + colg), b1v = __ldg(bias + colg + 1);
            float* q = acc[i*8+j];
            int rlo = row0 + m0w + i*16 + g;
            int rhi = rlo + 8;
            float o0 = elu_fast(q[0] + b0v), o1 = elu_fast(q[1] + b1v);
            float o2 = elu_fast(q[2] + b0v), o3 = elu_fast(q[3] + b1v);
            cs[j*2+0] += o0 + o2;
            cs[j*2+1] += o1 + o3;
            cq[j*2+0] += o0*o0 + o2*o2;
            cq[j*2+1] += o1*o1 + o3*o3;
            *(uint32_t*)(Cout + (size_t)rlo * 256 + colg) = pack_h2(__float2half_rn(o0), __float2half_rn(o1));
            *(uint32_t*)(Cout + (size_t)rhi * 256 + colg) = pack_h2(__float2half_rn(o2), __float2half_rn(o3));
        }
    }

    #pragma unroll
    for (int t = 0; t < 16; ++t) {
        #pragma unroll
        for (int o = 4; o <= 16; o <<= 1) {
            cs[t] += __shfl_xor_sync(0xffffffffu, cs[t], o);
            cq[t] += __shfl_xor_sync(0xffffffffu, cq[t], o);
        }
    }
    __syncthreads();
    float* sps = (float*)sm;
    if (lane < 4) {
        #pragma unroll
        for (int j = 0; j < 8; ++j) {
            #pragma unroll
            for (int par = 0; par < 2; ++par) {
                int coll = j*8 + lane*2 + par;
                sps[w*128 + coll*2 + 0] = cs[j*2+par];
                sps[w*128 + coll*2 + 1] = cq[j*2+par];
            }
        }
    }
    __syncthreads();
    int col = tid >> 1, stat = tid & 1;
    int nw4 = (col >> 6) * 4;
    float a2 = 0.f;
    #pragma unroll
    for (int mw = 0; mw < 4; ++mw)
        a2 += sps[(nw4 + mw)*128 + (col & 63)*2 + stat];
    g_p3[((size_t)blockIdx.x * 256 + col)*2 + stat] = a2;
    #undef CPA1
    #undef CPB1f
    #undef CPB2
}

// ---------------- edge2node: contiguous 99-edge segment mean (fp16 in) ------
__global__ void edge2node_k(const __half* __restrict__ x, float* __restrict__ out) {
    int nodeRow = blockIdx.x;
    int h = threadIdx.x;
    int b = nodeRow / Nn, n = nodeRow - b * Nn;
    const __half* base = x + (size_t)(b * Ee + n * 99) * Hh + h;
    float s = 0.f;
    #pragma unroll 3
    for (int r = 0; r < 99; r++) s += __half2float(base[(size_t)r * Hh]);
    out[(size_t)nodeRow * Hh + h] = s * (1.0f / 9900.0f);
}

// ---------------- BN partial reduce: parallel deterministic tree ------------
__global__ void bn_reduce_k() {
    int ch = blockIdx.x, t = threadIdx.x;
    double s = 0.0, q = 0.0;
    for (int bx = t; bx < NCTA; bx += 256) {
        s += (double)g_p3[((size_t)bx * 256 + ch) * 2 + 0];
        q += (double)g_p3[((size_t)bx * 256 + ch) * 2 + 1];
    }
    __shared__ double ss[256], sq[256];
    ss[t] = s; sq[t] = q;
    __syncthreads();
    for (int st = 128; st > 0; st >>= 1) {
        if (t < st) { ss[t] += ss[t + st]; sq[t] += sq[t + st]; }
        __syncthreads();
    }
    if (t == 0) { g_chS[ch] = ss[0]; g_chQ[ch] = sq[0]; }
}

// ---------------- BN finalize + fold into fc --------------------------------
__global__ void bn_fin3(const float* __restrict__ gamma, const float* __restrict__ beta,
                        const float* __restrict__ W, const float* __restrict__ fb) {
    int ch = threadIdx.x;
    double s = g_chS[ch], q = g_chQ[ch];
    double m = s / (double)BE;
    double v = q / (double)BE - m * m;
    float sc = (float)(rsqrt(v + 1e-5) * (double)gamma[ch]);
    float sh = beta[ch] - (float)m * sc;
    float w0 = W[ch*2 + 0], w1 = W[ch*2 + 1];
    g_fcW[ch*2 + 0] = sc * w0;
    g_fcW[ch*2 + 1] = sc * w1;
    __shared__ float r0s[256], r1s[256];
    r0s[ch] = sh * w0;
    r1s[ch] = sh * w1;
    __syncthreads();
    for (int st = 128; st > 0; st >>= 1) {
        if (ch < st) { r0s[ch] += r0s[ch + st]; r1s[ch] += r1s[ch + st]; }
        __syncthreads();
    }
    if (ch == 0) { g_fcB[0] = r0s[0] + fb[0]; g_fcB[1] = r1s[0] + fb[1]; }
}

// ---------------- final fc (folded BN): warp per row, fp16 y ----------------
__global__ void fc_k(const __half* __restrict__ y, float* __restrict__ out) {
    int gwarp = (blockIdx.x * blockDim.x + threadIdx.x) >> 5;
    int lane  = threadIdx.x & 31;
    if (gwarp >= BE) return;
    const __half2* row = (const __half2*)(y + (size_t)gwarp * Hh);
    float a0 = 0.f, a1 = 0.f;
    #pragma unroll
    for (int i = lane; i < 128; i += 32) {
        float2 v = __half22float2(row[i]);
        int ch = i * 2;
        a0 += v.x * g_fcW[ch*2 + 0] + v.y * g_fcW[ch*2 + 2];
        a1 += v.x * g_fcW[ch*2 + 1] + v.y * g_fcW[ch*2 + 3];
    }
    #pragma unroll
    for (int o = 16; o > 0; o >>= 1) {
        a0 += __shfl_down_sync(0xffffffffu, a0, o);
        a1 += __shfl_down_sync(0xffffffffu, a1, o);
    }
    if (lane == 0) {
        out[(size_t)gwarp * 2 + 0] = a0 + g_fcB[0];
        out[(size_t)gwarp * 2 + 1] = a1 + g_fcB[1];
    }
}

// ---------------------------------------------------------------------------
extern "C" void kernel_launch(void* const* d_in, const int* in_sizes, int n_in,
                              void* d_out, int out_size) {
    const float* inputs  = (const float*)d_in[0];
    const float* rel_rec = (const float*)d_in[1];
    const float* rel_snd = (const float*)d_in[2];
    const float* m1W1 = (const float*)d_in[3];  const float* m1b1 = (const float*)d_in[4];
    const float* m1W2 = (const float*)d_in[5];  const float* m1b2 = (const float*)d_in[6];
    const float* m2W1 = (const float*)d_in[7];  const float* m2b1 = (const float*)d_in[8];
    const float* m2W2 = (const float*)d_in[9];  const float* m2b2 = (const float*)d_in[10];
    const float* m3W1 = (const float*)d_in[11]; const float* m3b1 = (const float*)d_in[12];
    const float* m3W2 = (const float*)d_in[13]; const float* m3b2 = (const float*)d_in[14];
    const float* m4W1 = (const float*)d_in[15]; const float* m4b1 = (const float*)d_in[16];
    const float* m4W2 = (const float*)d_in[17]; const float* m4b2 = (const float*)d_in[18];
    const float* gmma = (const float*)d_in[19]; const float* beta = (const float*)d_in[20];
    const float* fcW  = (const float*)d_in[21]; const float* fcb  = (const float*)d_in[22];
    float* out = (float*)d_out;

    float *h1, *na, *nb, *as_, *ar_;
    __half *xskipH, *y4H, *wth;
    cudaGetSymbolAddress((void**)&h1, g_h1);
    cudaGetSymbolAddress((void**)&na, g_na);
    cudaGetSymbolAddress((void**)&nb, g_nb);
    cudaGetSymbolAddress((void**)&as_, g_as);
    cudaGetSymbolAddress((void**)&ar_, g_ar);
    cudaGetSymbolAddress((void**)&xskipH, g_xskipH);
    cudaGetSymbolAddress((void**)&y4H, g_y4H);
    cudaGetSymbolAddress((void**)&wth, g_WtHi);

    cudaFuncSetAttribute(gemm_g1,  cudaFuncAttributeMaxDynamicSharedMemorySize, G1DS);
    cudaFuncSetAttribute(gemm_f23, cudaFuncAttributeMaxDynamicSharedMemorySize, F_DS);
    cudaFuncSetAttribute(gemm_ntc, cudaFuncAttributeMaxDynamicSharedMemorySize, NDS);

    // one-shot weight prep: all 11 matrices
    PrepArgs pa;
    pa.src[0] = m2W2;              pa.K[0] = 256;
    pa.src[1] = m4W1 + 512 * 256;  pa.K[1] = 256;
    pa.src[2] = m4W2;              pa.K[2] = 256;
    pa.src[3] = m1W1;              pa.K[3] = FIN;   // 200, zero-padded
    pa.src[4] = m1W2;              pa.K[4] = 256;
    pa.src[5] = m2W1;              pa.K[5] = 256;   // send half
    pa.src[6] = m2W1 + 256 * 256;  pa.K[6] = 256;   // recv half
    pa.src[7] = m3W1;              pa.K[7] = 256;
    pa.src[8] = m3W2;              pa.K[8] = 256;
    pa.src[9] = m4W1;              pa.K[9] = 256;   // send half
    pa.src[10] = m4W1 + 256 * 256; pa.K[10] = 256;  // recv half

    build_idx_k<<<(Ee + 127) / 128, 128>>>(rel_rec, rel_snd);
    prep_all_k<<<dim3(8, 8, NWIMG), dim3(32, 32)>>>(pa);

    // mlp1 (node level, tensor 3-term)
    gemm_ntc<<<BNr/128, 512, NDS>>>(inputs, FIN, 3, 0, m1b1, 1, na, nullptr);
    gemm_ntc<<<BNr/128, 512, NDS>>>(na,     256, 4, 0, m1b2, 1, h1, nullptr);

    // node projections for mlp2 layer1 (dual)
    gemm_ntc<<<dim3(BNr/128, 2), 512, NDS>>>(h1, 256, 5, 6, nullptr, 0, as_, ar_);

    // GEMM1 (1-term W): xskipH = fp16(ELU(ELU(as[s]+ar[r]+b1) @ W2 + b2))
    gemm_g1<<<NCTA, 512, G1DS>>>(wth + 0 * 65536, as_, ar_, m2b1, m2b2, xskipH);

    // edge2node + mlp3 (node level, tensor)
    edge2node_k<<<BNr, 256>>>(xskipH, na);
    gemm_ntc<<<BNr/128, 512, NDS>>>(na, 256, 7, 0, m3b1, 1, nb, nullptr);
    gemm_ntc<<<BNr/128, 512, NDS>>>(nb, 256, 8, 0, m3b2, 1, h1, nullptr);

    // node projections for mlp4 layer1 (dual)
    gemm_ntc<<<dim3(BNr/128, 2), 512, NDS>>>(h1, 256, 9, 10, nullptr, 0, as_, ar_);

    // fused GEMM2+GEMM3 (both 1-term)
    gemm_f23<<<NCTA, 512, F_DS>>>(xskipH,
                                  wth + 1 * 65536,
                                  wth + 2 * 65536,
                                  as_, ar_, m4b1, m4b2, y4H);

    // BN reduce, finalize, final fc
    bn_reduce_k<<<256, 256>>>();
    bn_fin3<<<1, 256>>>(gmma, beta, fcW, fcb);
    fc_k<<<(BE * 32 + 255) / 256, 256>>>(y4H, out);
}